// round 2
// baseline (speedup 1.0000x reference)
#include <cuda_runtime.h>

// VQBlock: x [N=65536, D=256] fp32, dictionary [D=256, K=1024] fp32.
// out[0 .. N*D)  = q_st = x + (0.5*dict[:,argmin] - x)
// out[N*D]       = 1.25 * mean((x - q)^2)
//
// Round 2: same register-tiled fp32 GEMM, but the argmin now EMULATES the
// reference's fp32 rounding: dist = fl32( fl32(||f||^2 + ||d||^2) - 2*sim ),
// first-index tie-break. ||f||^2 and ||d||^2 computed in double, rounded to
// fp32 (best estimate of the reference's values; common-mode error in the
// row norm cannot reorder ties).

#define D_DIM 256
#define K_DIM 1024
#define N_ROWS 65536
#define TM 128
#define TN 128
#define KD 16

__device__ float  g_cnorm[K_DIM];          // ||dict[:,k]||^2 (fp32, from double)
__device__ float  g_rnorm[N_ROWS];         // ||x_row||^2 (fp32, from double)
__device__ float  g_dictT[K_DIM * D_DIM];  // transposed dictionary [K][D]
__device__ double g_sum;                   // sum of (x - q)^2

// ---------------------------------------------------------------------------
__global__ void colnorm_kernel(const float* __restrict__ dict) {
    int k = blockIdx.x * blockDim.x + threadIdx.x;
    if (k == 0) g_sum = 0.0;
    if (k < K_DIM) {
        double s = 0.0;
#pragma unroll 8
        for (int d = 0; d < D_DIM; d++) {
            double v = (double)dict[d * K_DIM + k];
            s += v * v;
        }
        g_cnorm[k] = (float)s;
    }
}

__global__ void rownorm_kernel(const float* __restrict__ x) {
    int warp = (blockIdx.x * blockDim.x + threadIdx.x) >> 5;
    int lane = threadIdx.x & 31;
    if (warp >= N_ROWS) return;
    const float4* p = (const float4*)(x + (size_t)warp * D_DIM);
    float4 a = p[lane];
    float4 b = p[lane + 32];
    double s = (double)a.x * a.x + (double)a.y * a.y
             + (double)a.z * a.z + (double)a.w * a.w
             + (double)b.x * b.x + (double)b.y * b.y
             + (double)b.z * b.z + (double)b.w * b.w;
#pragma unroll
    for (int o = 16; o > 0; o >>= 1)
        s += __shfl_xor_sync(0xffffffff, s, o);
    if (lane == 0) g_rnorm[warp] = (float)s;
}

__global__ void transpose_kernel(const float* __restrict__ dict) {
    int idx = blockIdx.x * blockDim.x + threadIdx.x;  // over K*D
    if (idx < K_DIM * D_DIM) {
        int d = idx >> 10;          // row of dict (K=1024 cols)
        int k = idx & (K_DIM - 1);
        g_dictT[k * D_DIM + d] = dict[idx];
    }
}

// ---------------------------------------------------------------------------
// One block: 128 rows x all 1024 codes, processed in 8 chunks of 128 codes.
// 256 threads, 8x8 microtile per thread.
__global__ __launch_bounds__(256) void vq_main(const float* __restrict__ x,
                                               const float* __restrict__ dict,
                                               float* __restrict__ out) {
    __shared__ float As[KD][TM];       // 8 KB
    __shared__ float Bs[KD][TN];       // 8 KB
    __shared__ float rs[TM][16];       // 8 KB
    __shared__ int   ri[TM][16];       // 8 KB
    __shared__ int   srow_k[TM];
    __shared__ double sred[256];

    const int tid = threadIdx.x;
    const int tx = tid & 15;
    const int ty = tid >> 4;
    const int row0 = blockIdx.x * TM;

    float best[8];
    int   bestk[8];
    float r8[8];
#pragma unroll
    for (int i = 0; i < 8; i++) {
        best[i] = 3.4e38f;
        bestk[i] = 0;
        r8[i] = g_rnorm[row0 + ty * 8 + i];
    }

    for (int chunk = 0; chunk < K_DIM; chunk += TN) {
        float acc[8][8];
#pragma unroll
        for (int i = 0; i < 8; i++)
#pragma unroll
            for (int j = 0; j < 8; j++) acc[i][j] = 0.f;

        for (int d0 = 0; d0 < D_DIM; d0 += KD) {
            float4 av[2], bv[2];
#pragma unroll
            for (int i = 0; i < 2; i++) {
                int q  = i * 256 + tid;        // 512 float4 for A-tile
                int r  = q >> 2;               // row 0..127
                int dq = q & 3;                // which float4 of the 16 depths
                av[i] = *(const float4*)(x + (size_t)(row0 + r) * D_DIM + d0 + dq * 4);
                int brow = q >> 5;             // depth row 0..15
                int bc   = (q & 31) * 4;       // col
                bv[i] = *(const float4*)(dict + (size_t)(d0 + brow) * K_DIM + chunk + bc);
            }
            __syncthreads();
#pragma unroll
            for (int i = 0; i < 2; i++) {
                int q  = i * 256 + tid;
                int r  = q >> 2;
                int dq = q & 3;
                As[dq * 4 + 0][r] = av[i].x;
                As[dq * 4 + 1][r] = av[i].y;
                As[dq * 4 + 2][r] = av[i].z;
                As[dq * 4 + 3][r] = av[i].w;
                int brow = q >> 5;
                int bc   = (q & 31) * 4;
                *(float4*)&Bs[brow][bc] = bv[i];
            }
            __syncthreads();
#pragma unroll
            for (int dd = 0; dd < KD; dd++) {
                float a[8], b[8];
                *(float4*)&a[0] = *(const float4*)&As[dd][ty * 8];
                *(float4*)&a[4] = *(const float4*)&As[dd][ty * 8 + 4];
                *(float4*)&b[0] = *(const float4*)&Bs[dd][tx * 8];
                *(float4*)&b[4] = *(const float4*)&Bs[dd][tx * 8 + 4];
#pragma unroll
                for (int i = 0; i < 8; i++)
#pragma unroll
                    for (int j = 0; j < 8; j++)
                        acc[i][j] += a[i] * b[j];
            }
        }

        // chunk epilogue: emulate reference fp32 rounding:
        //   dist = fl32( fl32(r + c_k) - 2*sim )   (2*sim is exact)
        // running argmin with first-index tie-break (strict < keeps lowest k).
#pragma unroll
        for (int j = 0; j < 8; j++) {
            int k = chunk + tx * 8 + j;
            float c = g_cnorm[k];
#pragma unroll
            for (int i = 0; i < 8; i++) {
                float t = __fadd_rn(r8[i], c);
                float dist = __fsub_rn(t, __fmul_rn(2.0f, acc[i][j]));
                if (dist < best[i]) { best[i] = dist; bestk[i] = k; }
            }
        }
    }

    __syncthreads();
#pragma unroll
    for (int i = 0; i < 8; i++) {
        rs[ty * 8 + i][tx] = best[i];
        ri[ty * 8 + i][tx] = bestk[i];
    }
    __syncthreads();
    if (tid < TM) {
        float b = rs[tid][0];
        int  bk = ri[tid][0];
#pragma unroll
        for (int t = 1; t < 16; t++) {
            float v = rs[tid][t];
            int  vk = ri[tid][t];
            if (v < b || (v == b && vk < bk)) { b = v; bk = vk; }
        }
        srow_k[tid] = bk;
    }
    __syncthreads();

    // write q_st (coalesced: tid maps to depth d) + accumulate squared error
    double lsum = 0.0;
    for (int e = tid; e < TM * D_DIM; e += 256) {
        int r = e >> 8;
        int d = e & 255;
        int k = srow_k[r];
        float qv = 0.5f * g_dictT[k * D_DIM + d];
        float xv = x[(size_t)(row0 + r) * D_DIM + d];
        out[(size_t)(row0 + r) * D_DIM + d] = __fadd_rn(xv, __fsub_rn(qv, xv));
        float diff = xv - qv;
        lsum += (double)diff * (double)diff;
    }
    sred[tid] = lsum;
    __syncthreads();
    for (int s = 128; s > 0; s >>= 1) {
        if (tid < s) sred[tid] += sred[tid + s];
        __syncthreads();
    }
    if (tid == 0) atomicAdd(&g_sum, sred[0]);
}

// ---------------------------------------------------------------------------
__global__ void finalize_kernel(float* out, long long total, int loss_idx) {
    out[loss_idx] = (float)(1.25 * g_sum / (double)total);
}

// ---------------------------------------------------------------------------
extern "C" void kernel_launch(void* const* d_in, const int* in_sizes, int n_in,
                              void* d_out, int out_size) {
    const float* x    = (const float*)d_in[0];
    const float* dict = (const float*)d_in[1];
    float* out = (float*)d_out;

    int Nel = in_sizes[0];     // N * D = 16777216
    int N   = Nel / D_DIM;     // 65536

    colnorm_kernel<<<(K_DIM + 255) / 256, 256>>>(dict);
    rownorm_kernel<<<(N * 32 + 255) / 256, 256>>>(x);
    transpose_kernel<<<(K_DIM * D_DIM + 255) / 256, 256>>>(dict);
    vq_main<<<N / TM, 256>>>(x, dict, out);
    if (out_size > Nel) {
        finalize_kernel<<<1, 1>>>(out, (long long)Nel, out_size - 1);
    }
}

// round 3
// speedup vs baseline: 1.0399x; 1.0399x over previous
#include <cuda_runtime.h>

// VQBlock: x [N=65536, D=256] fp32, dictionary [D=256, K=1024] fp32.
// out[0 .. N*D)  = q_st = x + (0.5*dict[:,argmin] - x)
// out[N*D]       = 1.25 * mean((x - q)^2)
//
// Round 3: same exact-fp32 GEMM + rounding-emulated argmin (bit-identical to
// R2, which scored rel_err = 0.0), but the inner product now uses packed
// fma.rn.f32x2 (sm_100+ FFMA2): 32 packed FMAs per depth step instead of 64
// scalar FFMA -> 2x fp32 math per issue slot.

#define D_DIM 256
#define K_DIM 1024
#define N_ROWS 65536
#define TM 128
#define TN 128
#define KD 16

__device__ float  g_cnorm[K_DIM];          // ||dict[:,k]||^2 (fp32, from double)
__device__ float  g_rnorm[N_ROWS];         // ||x_row||^2 (fp32, from double)
__device__ float  g_dictT[K_DIM * D_DIM];  // transposed dictionary [K][D]
__device__ double g_sum;                   // sum of (x - q)^2

// ---------------------------------------------------------------------------
__device__ __forceinline__ unsigned long long pack_dup(float v) {
    unsigned int b = __float_as_uint(v);
    unsigned long long r;
    asm("mov.b64 %0, {%1, %2};" : "=l"(r) : "r"(b), "r"(b));
    return r;
}

__device__ __forceinline__ void unpack2(unsigned long long p, float& lo, float& hi) {
    unsigned int a, b;
    asm("mov.b64 {%0, %1}, %2;" : "=r"(a), "=r"(b) : "l"(p));
    lo = __uint_as_float(a);
    hi = __uint_as_float(b);
}

__device__ __forceinline__ void ffma2(unsigned long long& acc,
                                      unsigned long long a,
                                      unsigned long long b) {
    asm("fma.rn.f32x2 %0, %1, %2, %0;" : "+l"(acc) : "l"(a), "l"(b));
}

// ---------------------------------------------------------------------------
__global__ void colnorm_kernel(const float* __restrict__ dict) {
    int k = blockIdx.x * blockDim.x + threadIdx.x;
    if (k == 0) g_sum = 0.0;
    if (k < K_DIM) {
        double s = 0.0;
#pragma unroll 8
        for (int d = 0; d < D_DIM; d++) {
            double v = (double)dict[d * K_DIM + k];
            s += v * v;
        }
        g_cnorm[k] = (float)s;
    }
}

__global__ void rownorm_kernel(const float* __restrict__ x) {
    int warp = (blockIdx.x * blockDim.x + threadIdx.x) >> 5;
    int lane = threadIdx.x & 31;
    if (warp >= N_ROWS) return;
    const float4* p = (const float4*)(x + (size_t)warp * D_DIM);
    float4 a = p[lane];
    float4 b = p[lane + 32];
    double s = (double)a.x * a.x + (double)a.y * a.y
             + (double)a.z * a.z + (double)a.w * a.w
             + (double)b.x * b.x + (double)b.y * b.y
             + (double)b.z * b.z + (double)b.w * b.w;
#pragma unroll
    for (int o = 16; o > 0; o >>= 1)
        s += __shfl_xor_sync(0xffffffff, s, o);
    if (lane == 0) g_rnorm[warp] = (float)s;
}

__global__ void transpose_kernel(const float* __restrict__ dict) {
    int idx = blockIdx.x * blockDim.x + threadIdx.x;  // over K*D
    if (idx < K_DIM * D_DIM) {
        int d = idx >> 10;          // row of dict (K=1024 cols)
        int k = idx & (K_DIM - 1);
        g_dictT[k * D_DIM + d] = dict[idx];
    }
}

// ---------------------------------------------------------------------------
// One block: 128 rows x all 1024 codes, processed in 8 chunks of 128 codes.
// 256 threads, 8 rows x 4 column-pairs microtile per thread (FFMA2).
__global__ __launch_bounds__(256) void vq_main(const float* __restrict__ x,
                                               const float* __restrict__ dict,
                                               float* __restrict__ out) {
    __shared__ float As[KD][TM];       // 8 KB
    __shared__ float Bs[KD][TN];       // 8 KB
    __shared__ float rs[TM][16];       // 8 KB
    __shared__ int   ri[TM][16];       // 8 KB
    __shared__ int   srow_k[TM];
    __shared__ double sred[256];

    const int tid = threadIdx.x;
    const int tx = tid & 15;
    const int ty = tid >> 4;
    const int row0 = blockIdx.x * TM;

    float best[8];
    int   bestk[8];
    float r8[8];
#pragma unroll
    for (int i = 0; i < 8; i++) {
        best[i] = 3.4e38f;
        bestk[i] = 0;
        r8[i] = g_rnorm[row0 + ty * 8 + i];
    }

    for (int chunk = 0; chunk < K_DIM; chunk += TN) {
        unsigned long long acc2[8][4];   // 8 rows x 4 col-pairs, packed f32x2
#pragma unroll
        for (int i = 0; i < 8; i++)
#pragma unroll
            for (int j = 0; j < 4; j++) acc2[i][j] = 0ull;

        for (int d0 = 0; d0 < D_DIM; d0 += KD) {
            float4 av[2], bv[2];
#pragma unroll
            for (int i = 0; i < 2; i++) {
                int q  = i * 256 + tid;        // 512 float4 for A-tile
                int r  = q >> 2;               // row 0..127
                int dq = q & 3;                // which float4 of the 16 depths
                av[i] = *(const float4*)(x + (size_t)(row0 + r) * D_DIM + d0 + dq * 4);
                int brow = q >> 5;             // depth row 0..15
                int bc   = (q & 31) * 4;       // col
                bv[i] = *(const float4*)(dict + (size_t)(d0 + brow) * K_DIM + chunk + bc);
            }
            __syncthreads();
#pragma unroll
            for (int i = 0; i < 2; i++) {
                int q  = i * 256 + tid;
                int r  = q >> 2;
                int dq = q & 3;
                As[dq * 4 + 0][r] = av[i].x;
                As[dq * 4 + 1][r] = av[i].y;
                As[dq * 4 + 2][r] = av[i].z;
                As[dq * 4 + 3][r] = av[i].w;
                int brow = q >> 5;
                int bc   = (q & 31) * 4;
                *(float4*)&Bs[brow][bc] = bv[i];
            }
            __syncthreads();
#pragma unroll
            for (int dd = 0; dd < KD; dd++) {
                float a[8];
                *(float4*)&a[0] = *(const float4*)&As[dd][ty * 8];
                *(float4*)&a[4] = *(const float4*)&As[dd][ty * 8 + 4];
                // Bs row chunk is 32B aligned: reinterpret as packed pairs
                unsigned long long b2[4];
                *(ulonglong2*)&b2[0] = *(const ulonglong2*)&Bs[dd][tx * 8];
                *(ulonglong2*)&b2[2] = *(const ulonglong2*)&Bs[dd][tx * 8 + 4];
#pragma unroll
                for (int i = 0; i < 8; i++) {
                    unsigned long long a2 = pack_dup(a[i]);
#pragma unroll
                    for (int j = 0; j < 4; j++)
                        ffma2(acc2[i][j], a2, b2[j]);
                }
            }
        }

        // chunk epilogue: emulate reference fp32 rounding:
        //   dist = fl32( fl32(r + c_k) - 2*sim )   (2*sim is exact)
        // running argmin with first-index tie-break (strict < keeps lowest k).
#pragma unroll
        for (int j = 0; j < 4; j++) {
            int k0 = chunk + tx * 8 + 2 * j;
            float c0 = g_cnorm[k0];
            float c1 = g_cnorm[k0 + 1];
#pragma unroll
            for (int i = 0; i < 8; i++) {
                float s0, s1;
                unpack2(acc2[i][j], s0, s1);
                float d0v = __fsub_rn(__fadd_rn(r8[i], c0), __fmul_rn(2.0f, s0));
                float d1v = __fsub_rn(__fadd_rn(r8[i], c1), __fmul_rn(2.0f, s1));
                if (d0v < best[i]) { best[i] = d0v; bestk[i] = k0; }
                if (d1v < best[i]) { best[i] = d1v; bestk[i] = k0 + 1; }
            }
        }
    }

    __syncthreads();
#pragma unroll
    for (int i = 0; i < 8; i++) {
        rs[ty * 8 + i][tx] = best[i];
        ri[ty * 8 + i][tx] = bestk[i];
    }
    __syncthreads();
    if (tid < TM) {
        float b = rs[tid][0];
        int  bk = ri[tid][0];
#pragma unroll
        for (int t = 1; t < 16; t++) {
            float v = rs[tid][t];
            int  vk = ri[tid][t];
            if (v < b || (v == b && vk < bk)) { b = v; bk = vk; }
        }
        srow_k[tid] = bk;
    }
    __syncthreads();

    // write q_st (coalesced: tid maps to depth d) + accumulate squared error
    double lsum = 0.0;
    for (int e = tid; e < TM * D_DIM; e += 256) {
        int r = e >> 8;
        int d = e & 255;
        int k = srow_k[r];
        float qv = 0.5f * g_dictT[k * D_DIM + d];
        float xv = x[(size_t)(row0 + r) * D_DIM + d];
        out[(size_t)(row0 + r) * D_DIM + d] = __fadd_rn(xv, __fsub_rn(qv, xv));
        float diff = xv - qv;
        lsum += (double)diff * (double)diff;
    }
    sred[tid] = lsum;
    __syncthreads();
    for (int s = 128; s > 0; s >>= 1) {
        if (tid < s) sred[tid] += sred[tid + s];
        __syncthreads();
    }
    if (tid == 0) atomicAdd(&g_sum, sred[0]);
}

// ---------------------------------------------------------------------------
__global__ void finalize_kernel(float* out, long long total, int loss_idx) {
    out[loss_idx] = (float)(1.25 * g_sum / (double)total);
}

// ---------------------------------------------------------------------------
extern "C" void kernel_launch(void* const* d_in, const int* in_sizes, int n_in,
                              void* d_out, int out_size) {
    const float* x    = (const float*)d_in[0];
    const float* dict = (const float*)d_in[1];
    float* out = (float*)d_out;

    int Nel = in_sizes[0];     // N * D = 16777216
    int N   = Nel / D_DIM;     // 65536

    colnorm_kernel<<<(K_DIM + 255) / 256, 256>>>(dict);
    rownorm_kernel<<<(N * 32 + 255) / 256, 256>>>(x);
    transpose_kernel<<<(K_DIM * D_DIM + 255) / 256, 256>>>(dict);
    vq_main<<<N / TM, 256>>>(x, dict, out);
    if (out_size > Nel) {
        finalize_kernel<<<1, 1>>>(out, (long long)Nel, out_size - 1);
    }
}